// round 8
// baseline (speedup 1.0000x reference)
#include <cuda_runtime.h>
#include <cstdint>

#define Bb 32
#define Cc 32
#define Tt 2048
#define Dd 512
#define ALPHA 0.1f
#define BETA  0.9f

#define SEG   128
#define NSEG  (Tt / SEG)          // 16
#define NSCAN_BLK ((Bb * Cc * NSEG * 2) / 8)   // 4096 scan blocks, 8 warps each

// Scratch (no cudaMalloc allowed)
__device__ float g_sA[Bb*Cc*Tt];      // 0.5 * forward EWMA of diff   [b][c][t]
__device__ float g_sB[Bb*Cc*Tt];      // 0.5 * backward EWMA of diff  [b][c][t]
__device__ float g_wc[Cc*Dd];         // Wcomb c-major: g_wc[c*Dd + e]
__device__ float g_bcomb[Dd];         // W_lin @ b_ve + b_lin

#define FMA_F32X2(d, a, b, c) \
    asm("fma.rn.f32x2 %0, %1, %2, %3;" : "=l"(d) : "l"(a), "l"(b), "l"(c))

static __device__ __forceinline__ float2 unpack_f32x2(unsigned long long v) {
    float2 r;
    asm("mov.b64 {%0, %1}, %2;" : "=f"(r.x), "=f"(r.y) : "l"(v));
    return r;
}

// ---------------------------------------------------------------------------
// SP: merged scan + prep. Blocks [0, NSCAN_BLK) do the bidirectional EWMA
// scan (SEG=128, one warm chunk, lane-serial E=4); blocks [NSCAN_BLK, +Dd)
// compose the linears (one block per output row e).
// ---------------------------------------------------------------------------
__global__ void __launch_bounds__(256) sp_kernel(
    const float* __restrict__ x,
    const float* __restrict__ W_ve, const float* __restrict__ b_ve,
    const float* __restrict__ W_lin, const float* __restrict__ b_lin)
{
    const unsigned FULL = 0xffffffffu;
    int tid = threadIdx.x;

    if (blockIdx.x >= NSCAN_BLK) {
        // ---------------- prep part ----------------
        __shared__ float wl[Dd];
        int e = blockIdx.x - NSCAN_BLK;
        wl[tid]       = W_lin[(size_t)e * Dd + tid];
        wl[tid + 256] = W_lin[(size_t)e * Dd + tid + 256];
        __syncthreads();

        int wj   = tid >> 5;
        int lane = tid & 31;
        for (int c = wj; c <= Cc; c += 8) {
            float acc = 0.f;
            if (c < Cc) {
                #pragma unroll
                for (int i = 0; i < 16; i++) {
                    int d = lane + 32 * i;
                    acc = fmaf(wl[d], W_ve[d * Cc + c], acc);
                }
            } else {
                #pragma unroll
                for (int i = 0; i < 16; i++) {
                    int d = lane + 32 * i;
                    acc = fmaf(wl[d], b_ve[d], acc);
                }
            }
            acc += __shfl_down_sync(FULL, acc, 16);
            acc += __shfl_down_sync(FULL, acc, 8);
            acc += __shfl_down_sync(FULL, acc, 4);
            acc += __shfl_down_sync(FULL, acc, 2);
            acc += __shfl_down_sync(FULL, acc, 1);
            if (lane == 0) {
                if (c < Cc) g_wc[c * Dd + e] = acc;
                else        g_bcomb[e] = acc + b_lin[e];
            }
        }
        return;
    }

    // ---------------- scan part ----------------
    int g    = blockIdx.x * 8 + (tid >> 5);
    int lane = tid & 31;
    int bc   = g >> 5;            // row (b*Cc + c); 32 warps per row
    int rem  = g & 31;
    int seg  = rem >> 1;          // 0..15
    int dir  = rem & 1;

    const float* row = x + (size_t)bc * Tt;
    int lo = seg * SEG;
    int hi = lo + SEG;

    // q = beta^4 and squarings; blE = beta^(4*lane)
    const float q   = 0.6561f;                  // 0.9^4
    const float q2  = q * q;
    const float q4  = q2 * q2;
    const float q8  = q4 * q4;
    const float q16 = q8 * q8;
    float blE;
    {
        float p = 1.f, base = q;
        int n = lane;
        while (n) { if (n & 1) p *= base; base *= base; n >>= 1; }
        blE = p;
    }
    const float B128 = 1.3925e-6f;              // ~0.9^128 (negligible truncation)

    if (dir == 0) {
        float* srow = g_sA + (size_t)bc * Tt;
        int t0 = (seg == 0) ? lo : (lo - SEG);
        float warpCarry = 0.f;
        for (; t0 < hi; t0 += SEG) {
            int tb = t0 + lane * 4;
            float4 a = *(const float4*)(row + tb);
            float e[4] = {a.x, a.y, a.z, a.w};
            float prev = __shfl_up_sync(FULL, a.w, 1);
            if (lane == 0) prev = (tb > 0) ? row[tb - 1] : 0.f;

            float L[4];
            L[0] = (tb == 0) ? 0.f : ALPHA * (e[0] - prev);
            #pragma unroll
            for (int j = 1; j < 4; j++)
                L[j] = fmaf(BETA, L[j - 1], ALPHA * (e[j] - e[j - 1]));

            float v = L[3], vo;
            vo = __shfl_up_sync(FULL, v, 1);  if (lane >= 1)  v = fmaf(q,   vo, v);
            vo = __shfl_up_sync(FULL, v, 2);  if (lane >= 2)  v = fmaf(q2,  vo, v);
            vo = __shfl_up_sync(FULL, v, 4);  if (lane >= 4)  v = fmaf(q4,  vo, v);
            vo = __shfl_up_sync(FULL, v, 8);  if (lane >= 8)  v = fmaf(q8,  vo, v);
            vo = __shfl_up_sync(FULL, v, 16); if (lane >= 16) v = fmaf(q16, vo, v);
            float vprev = __shfl_up_sync(FULL, v, 1);
            if (lane == 0) vprev = 0.f;
            float C = fmaf(blE, warpCarry, vprev);

            float F[4];
            float coef = BETA;
            #pragma unroll
            for (int j = 0; j < 4; j++) { F[j] = fmaf(coef, C, L[j]); coef *= BETA; }
            float v31 = __shfl_sync(FULL, v, 31);
            warpCarry = fmaf(B128, warpCarry, v31);

            if (t0 >= lo)
                *(float4*)(srow + tb) = make_float4(0.5f*F[0], 0.5f*F[1], 0.5f*F[2], 0.5f*F[3]);
        }
    } else {
        float* srow = g_sB + (size_t)bc * Tt;
        bool last = (hi == Tt);
        int tt = last ? (Tt - 1) : (hi + SEG - 1);
        // exact right-boundary init: carry = d_{T-1}; beta=1-alpha makes
        // the standard recurrence reproduce g_{T-1} = d_{T-1}.
        float warpCarry = last ? (row[Tt - 1] - row[Tt - 2]) : 0.f;
        for (; tt >= lo; tt -= SEG) {
            int tb = tt - lane * 4;                    // memory [tb-3, tb]
            float4 a = *(const float4*)(row + tb - 3); // row[tb-3..tb]
            float e[4] = {a.w, a.z, a.y, a.x};         // e[j] = row[tb-j]
            float prev = __shfl_down_sync(FULL, a.w, 1);  // lane+1's row[tb-4]
            if (lane == 31) prev = (tb - 4 >= 0) ? row[tb - 4] : 0.f;

            float L[4];
            L[0] = ALPHA * (e[0] - e[1]);
            L[1] = fmaf(BETA, L[0], ALPHA * (e[1] - e[2]));
            L[2] = fmaf(BETA, L[1], ALPHA * (e[2] - e[3]));
            {
                float d3 = (tb - 3 == 0) ? 0.f : (e[3] - prev);
                L[3] = fmaf(BETA, L[2], ALPHA * d3);
            }

            float v = L[3], vo;
            vo = __shfl_up_sync(FULL, v, 1);  if (lane >= 1)  v = fmaf(q,   vo, v);
            vo = __shfl_up_sync(FULL, v, 2);  if (lane >= 2)  v = fmaf(q2,  vo, v);
            vo = __shfl_up_sync(FULL, v, 4);  if (lane >= 4)  v = fmaf(q4,  vo, v);
            vo = __shfl_up_sync(FULL, v, 8);  if (lane >= 8)  v = fmaf(q8,  vo, v);
            vo = __shfl_up_sync(FULL, v, 16); if (lane >= 16) v = fmaf(q16, vo, v);
            float vprev = __shfl_up_sync(FULL, v, 1);
            if (lane == 0) vprev = 0.f;
            float C = fmaf(blE, warpCarry, vprev);

            float F[4];
            float coef = BETA;
            #pragma unroll
            for (int j = 0; j < 4; j++) { F[j] = fmaf(coef, C, L[j]); coef *= BETA; }
            float v31 = __shfl_sync(FULL, v, 31);
            warpCarry = fmaf(B128, warpCarry, v31);

            if (tt < hi)
                *(float4*)(srow + tb - 3) = make_float4(0.5f*F[3], 0.5f*F[2], 0.5f*F[1], 0.5f*F[0]);
        }
    }
}

// ---------------------------------------------------------------------------
// G: register-blocked FFMA2 GEMM.
// Block tile 128t x 128e, 256 threads (tx 0..15 -> e, ty 0..15 -> t).
// Thread tile 8t x 8e with e = eBase + 4*tx + 64*p + j (p=0..1, j=0..3):
// w loads are 2x LDS.128 per c, stores are 2x STG.128 per t-row.
// s tile stored duplicated (v,v) so broadcast pairs come from LDS.128.
// ---------------------------------------------------------------------------
__global__ void __launch_bounds__(256, 2) gemm_kernel(float* __restrict__ out)
{
    __shared__ float2 dssm[Cc][128];   // [c][t_local] duplicated (v,v), 32 KB
    __shared__ float  wsm[Cc][128];    // [c][e_local] natural, 16 KB

    int tid = threadIdx.x;
    int tx = tid & 15;
    int ty = tid >> 4;
    int b = blockIdx.z;
    int eBase = blockIdx.y * 128;
    int tBase = blockIdx.x * 128;

    // Stage s: 32c x 128t; coalesced float4 over t; store duplicated pairs.
    #pragma unroll
    for (int k = 0; k < 4; k++) {
        int idx = tid + k * 256;          // 0..1023
        int c   = idx >> 5;               // 0..31
        int tl  = (idx & 31) * 4;         // 0..124
        size_t off = ((size_t)(b * Cc + c)) * Tt + tBase + tl;
        float4 a  = *(const float4*)(g_sA + off);
        float4 bq = *(const float4*)(g_sB + off);
        float v0 = a.x + bq.x, v1 = a.y + bq.y, v2 = a.z + bq.z, v3 = a.w + bq.w;
        float4* d = (float4*)&dssm[c][tl];
        d[0] = make_float4(v0, v0, v1, v1);
        d[1] = make_float4(v2, v2, v3, v3);
    }
    // Stage w: 32c x 128e, natural layout.
    #pragma unroll
    for (int k = 0; k < 4; k++) {
        int idx = tid + k * 256;
        int c   = idx >> 5;
        int e4  = (idx & 31) * 4;
        *(float4*)&wsm[c][e4] = *(const float4*)(g_wc + (size_t)c * Dd + eBase + e4);
    }
    __syncthreads();

    unsigned long long acc[8][4];      // [t][p*2+half]; halves are e-pairs
    #pragma unroll
    for (int i = 0; i < 8; i++)
        #pragma unroll
        for (int p = 0; p < 4; p++) acc[i][p] = 0ull;

    #pragma unroll
    for (int c = 0; c < Cc; c++) {
        const ulonglong2* sp = (const ulonglong2*)&dssm[c][ty * 8];
        ulonglong2 s01 = sp[0];
        ulonglong2 s23 = sp[1];
        ulonglong2 s45 = sp[2];
        ulonglong2 s67 = sp[3];
        unsigned long long sv[8] = {s01.x, s01.y, s23.x, s23.y,
                                    s45.x, s45.y, s67.x, s67.y};
        ulonglong2 w0 = *(const ulonglong2*)&wsm[c][4 * tx];        // e pairs (0,1),(2,3)
        ulonglong2 w1 = *(const ulonglong2*)&wsm[c][4 * tx + 64];   // e pairs +64
        #pragma unroll
        for (int i = 0; i < 8; i++) {
            FMA_F32X2(acc[i][0], sv[i], w0.x, acc[i][0]);
            FMA_F32X2(acc[i][1], sv[i], w0.y, acc[i][1]);
            FMA_F32X2(acc[i][2], sv[i], w1.x, acc[i][2]);
            FMA_F32X2(acc[i][3], sv[i], w1.y, acc[i][3]);
        }
    }

    // Epilogue: bias + 2x STG.128 per t-row.
    float4 bias0 = *(const float4*)(g_bcomb + eBase + 4 * tx);
    float4 bias1 = *(const float4*)(g_bcomb + eBase + 4 * tx + 64);

    #pragma unroll
    for (int i = 0; i < 8; i++) {
        int t = tBase + ty * 8 + i;
        float* base = out + ((size_t)(b * Tt + t)) * Dd + eBase;
        float2 r0 = unpack_f32x2(acc[i][0]);
        float2 r1 = unpack_f32x2(acc[i][1]);
        float2 r2 = unpack_f32x2(acc[i][2]);
        float2 r3 = unpack_f32x2(acc[i][3]);
        float4 o0 = make_float4(r0.x + bias0.x, r0.y + bias0.y,
                                r1.x + bias0.z, r1.y + bias0.w);
        float4 o1 = make_float4(r2.x + bias1.x, r2.y + bias1.y,
                                r3.x + bias1.z, r3.y + bias1.w);
        *(float4*)(base + 4 * tx)      = o0;
        *(float4*)(base + 4 * tx + 64) = o1;
    }
}

// ---------------------------------------------------------------------------
extern "C" void kernel_launch(void* const* d_in, const int* in_sizes, int n_in,
                              void* d_out, int out_size)
{
    const float* x     = (const float*)d_in[0];   // [B, C, T]
    const float* W_ve  = (const float*)d_in[1];   // [D, C]
    const float* b_ve  = (const float*)d_in[2];   // [D]
    const float* W_lin = (const float*)d_in[3];   // [D, D]
    const float* b_lin = (const float*)d_in[4];   // [D]
    float* out = (float*)d_out;                   // [B, T, D]

    // SP: scan (4096 blocks) + prep (512 blocks) in one launch
    sp_kernel<<<NSCAN_BLK + Dd, 256>>>(x, W_ve, b_ve, W_lin, b_lin);

    // G: FFMA2 GEMM + bias
    dim3 grid(Tt / 128, Dd / 128, Bb);
    gemm_kernel<<<grid, 256>>>(out);
}

// round 9
// speedup vs baseline: 1.4611x; 1.4611x over previous
#include <cuda_runtime.h>
#include <cstdint>

#define Bb 32
#define Cc 32
#define Tt 2048
#define Dd 512
#define ALPHA 0.1f
#define BETA  0.9f

#define SEG   128
#define NSEG  (Tt / SEG)          // 16
#define NSCAN_BLK ((Bb * Cc * NSEG * 2) / 8)   // 4096 scan blocks

// Scratch (no cudaMalloc allowed)
__device__ float g_sA[Bb*Cc*Tt];      // 0.5 * forward EWMA of diff   [b][c][t]
__device__ float g_sB[Bb*Cc*Tt];      // 0.5 * backward EWMA of diff  [b][c][t]
__device__ float g_wc[Cc*Dd];         // Wcomb c-major: g_wc[c*Dd + e]
__device__ float g_bcomb[Dd];         // W_lin @ b_ve + b_lin

#define FMA_F32X2(d, a, b, c) \
    asm("fma.rn.f32x2 %0, %1, %2, %3;" : "=l"(d) : "l"(a), "l"(b), "l"(c))

static __device__ __forceinline__ float2 unpack_f32x2(unsigned long long v) {
    float2 r;
    asm("mov.b64 {%0, %1}, %2;" : "=f"(r.x), "=f"(r.y) : "l"(v));
    return r;
}

// ---------------------------------------------------------------------------
// P: smem-tiled mini-GEMM for Wcomb = W_lin @ W_ve (c-major out) + bias.
// Grid: 32 blocks x 16 e-rows. 256 threads: tx=c-pair (16), ty=e (16).
// d processed in 4 chunks of 128; all global loads coalesced; LDS
// conflict-free (wlin stride 17, wve stride 36).
// ---------------------------------------------------------------------------
#define PE 16
__global__ void __launch_bounds__(256) prep_kernel(
    const float* __restrict__ W_ve, const float* __restrict__ b_ve,
    const float* __restrict__ W_lin, const float* __restrict__ b_lin)
{
    __shared__ float wlin_sm[128 * 17];   // [d][e] transposed, pad 17
    __shared__ float wve_sm[128 * 36];    // [d][c], pad 36 (16B-aligned rows)

    int tid = threadIdx.x;
    int e0 = blockIdx.x * PE;
    int tx = tid & 15;       // c-pair: c = 2*tx
    int ty = tid >> 4;       // e-row

    float2 acc = make_float2(0.f, 0.f);

    for (int ch = 0; ch < 4; ch++) {
        int dBase = ch * 128;
        __syncthreads();     // previous chunk fully consumed

        // Load W_lin chunk transposed: 16e x 128d, coalesced float4.
        #pragma unroll
        for (int k = 0; k < 2; k++) {
            int idx = tid + k * 256;          // 0..511
            int e   = idx >> 5;               // 0..15
            int d4  = (idx & 31) * 4;         // 0..124
            float4 w = *(const float4*)(W_lin + (size_t)(e0 + e) * Dd + dBase + d4);
            wlin_sm[(d4 + 0) * 17 + e] = w.x;
            wlin_sm[(d4 + 1) * 17 + e] = w.y;
            wlin_sm[(d4 + 2) * 17 + e] = w.z;
            wlin_sm[(d4 + 3) * 17 + e] = w.w;
        }
        // Load W_ve chunk: 128d x 32c, coalesced float4.
        #pragma unroll
        for (int k = 0; k < 4; k++) {
            int idx = tid + k * 256;          // 0..1023
            int d   = idx >> 3;               // 0..127
            int c4  = (idx & 7) * 4;          // 0..28
            float4 v = *(const float4*)(W_ve + (size_t)(dBase + d) * Cc + c4);
            *(float4*)&wve_sm[d * 36 + c4] = v;
        }
        __syncthreads();

        #pragma unroll 8
        for (int dl = 0; dl < 128; dl++) {
            float  wl  = wlin_sm[dl * 17 + ty];
            float2 wv2 = *(const float2*)&wve_sm[dl * 36 + tx * 2];
            acc.x = fmaf(wl, wv2.x, acc.x);
            acc.y = fmaf(wl, wv2.y, acc.y);
        }
    }

    // Write Wcomb c-major.
    int e = e0 + ty;
    g_wc[(2 * tx)     * Dd + e] = acc.x;
    g_wc[(2 * tx + 1) * Dd + e] = acc.y;

    // Bias: warp w handles e_local = 2w, 2w+1; coalesced W_lin row reads.
    const unsigned FULL = 0xffffffffu;
    int wid  = tid >> 5;
    int lane = tid & 31;
    #pragma unroll
    for (int r = 0; r < 2; r++) {
        int eb = e0 + 2 * wid + r;
        float a = 0.f;
        #pragma unroll
        for (int i = 0; i < 16; i++) {
            int d = lane + 32 * i;
            a = fmaf(W_lin[(size_t)eb * Dd + d], b_ve[d], a);
        }
        a += __shfl_down_sync(FULL, a, 16);
        a += __shfl_down_sync(FULL, a, 8);
        a += __shfl_down_sync(FULL, a, 4);
        a += __shfl_down_sync(FULL, a, 2);
        a += __shfl_down_sync(FULL, a, 1);
        if (lane == 0) g_bcomb[eb] = a + b_lin[eb];
    }
}

// ---------------------------------------------------------------------------
// S: bidirectional EWMA of first-difference (SEG=128, lane-serial E=4).
// ---------------------------------------------------------------------------
__global__ void __launch_bounds__(256) scan_kernel(const float* __restrict__ x)
{
    const unsigned FULL = 0xffffffffu;
    int tid  = threadIdx.x;
    int g    = blockIdx.x * 8 + (tid >> 5);
    int lane = tid & 31;
    int bc   = g >> 5;            // row (b*Cc + c); 32 warps per row
    int rem  = g & 31;
    int seg  = rem >> 1;
    int dir  = rem & 1;

    const float* row = x + (size_t)bc * Tt;
    int lo = seg * SEG;
    int hi = lo + SEG;

    const float q   = 0.6561f;                  // 0.9^4
    const float q2  = q * q;
    const float q4  = q2 * q2;
    const float q8  = q4 * q4;
    const float q16 = q8 * q8;
    float blE;
    {
        float p = 1.f, base = q;
        int n = lane;
        while (n) { if (n & 1) p *= base; base *= base; n >>= 1; }
        blE = p;
    }
    const float B128 = 1.3925e-6f;

    if (dir == 0) {
        float* srow = g_sA + (size_t)bc * Tt;
        int t0 = (seg == 0) ? lo : (lo - SEG);
        float warpCarry = 0.f;
        for (; t0 < hi; t0 += SEG) {
            int tb = t0 + lane * 4;
            float4 a = *(const float4*)(row + tb);
            float e[4] = {a.x, a.y, a.z, a.w};
            float prev = __shfl_up_sync(FULL, a.w, 1);
            if (lane == 0) prev = (tb > 0) ? row[tb - 1] : 0.f;

            float L[4];
            L[0] = (tb == 0) ? 0.f : ALPHA * (e[0] - prev);
            #pragma unroll
            for (int j = 1; j < 4; j++)
                L[j] = fmaf(BETA, L[j - 1], ALPHA * (e[j] - e[j - 1]));

            float v = L[3], vo;
            vo = __shfl_up_sync(FULL, v, 1);  if (lane >= 1)  v = fmaf(q,   vo, v);
            vo = __shfl_up_sync(FULL, v, 2);  if (lane >= 2)  v = fmaf(q2,  vo, v);
            vo = __shfl_up_sync(FULL, v, 4);  if (lane >= 4)  v = fmaf(q4,  vo, v);
            vo = __shfl_up_sync(FULL, v, 8);  if (lane >= 8)  v = fmaf(q8,  vo, v);
            vo = __shfl_up_sync(FULL, v, 16); if (lane >= 16) v = fmaf(q16, vo, v);
            float vprev = __shfl_up_sync(FULL, v, 1);
            if (lane == 0) vprev = 0.f;
            float C = fmaf(blE, warpCarry, vprev);

            float F[4];
            float coef = BETA;
            #pragma unroll
            for (int j = 0; j < 4; j++) { F[j] = fmaf(coef, C, L[j]); coef *= BETA; }
            float v31 = __shfl_sync(FULL, v, 31);
            warpCarry = fmaf(B128, warpCarry, v31);

            if (t0 >= lo)
                *(float4*)(srow + tb) = make_float4(0.5f*F[0], 0.5f*F[1], 0.5f*F[2], 0.5f*F[3]);
        }
    } else {
        float* srow = g_sB + (size_t)bc * Tt;
        bool last = (hi == Tt);
        int tt = last ? (Tt - 1) : (hi + SEG - 1);
        float warpCarry = last ? (row[Tt - 1] - row[Tt - 2]) : 0.f;
        for (; tt >= lo; tt -= SEG) {
            int tb = tt - lane * 4;
            float4 a = *(const float4*)(row + tb - 3);
            float e[4] = {a.w, a.z, a.y, a.x};
            float prev = __shfl_down_sync(FULL, a.w, 1);
            if (lane == 31) prev = (tb - 4 >= 0) ? row[tb - 4] : 0.f;

            float L[4];
            L[0] = ALPHA * (e[0] - e[1]);
            L[1] = fmaf(BETA, L[0], ALPHA * (e[1] - e[2]));
            L[2] = fmaf(BETA, L[1], ALPHA * (e[2] - e[3]));
            {
                float d3 = (tb - 3 == 0) ? 0.f : (e[3] - prev);
                L[3] = fmaf(BETA, L[2], ALPHA * d3);
            }

            float v = L[3], vo;
            vo = __shfl_up_sync(FULL, v, 1);  if (lane >= 1)  v = fmaf(q,   vo, v);
            vo = __shfl_up_sync(FULL, v, 2);  if (lane >= 2)  v = fmaf(q2,  vo, v);
            vo = __shfl_up_sync(FULL, v, 4);  if (lane >= 4)  v = fmaf(q4,  vo, v);
            vo = __shfl_up_sync(FULL, v, 8);  if (lane >= 8)  v = fmaf(q8,  vo, v);
            vo = __shfl_up_sync(FULL, v, 16); if (lane >= 16) v = fmaf(q16, vo, v);
            float vprev = __shfl_up_sync(FULL, v, 1);
            if (lane == 0) vprev = 0.f;
            float C = fmaf(blE, warpCarry, vprev);

            float F[4];
            float coef = BETA;
            #pragma unroll
            for (int j = 0; j < 4; j++) { F[j] = fmaf(coef, C, L[j]); coef *= BETA; }
            float v31 = __shfl_sync(FULL, v, 31);
            warpCarry = fmaf(B128, warpCarry, v31);

            if (tt < hi)
                *(float4*)(srow + tb - 3) = make_float4(0.5f*F[3], 0.5f*F[2], 0.5f*F[1], 0.5f*F[0]);
        }
    }
}

// ---------------------------------------------------------------------------
// G: register-blocked FFMA2 GEMM (identical to R8's measured 52.5us version).
// ---------------------------------------------------------------------------
__global__ void __launch_bounds__(256, 2) gemm_kernel(float* __restrict__ out)
{
    __shared__ float2 dssm[Cc][128];
    __shared__ float  wsm[Cc][128];

    int tid = threadIdx.x;
    int tx = tid & 15;
    int ty = tid >> 4;
    int b = blockIdx.z;
    int eBase = blockIdx.y * 128;
    int tBase = blockIdx.x * 128;

    #pragma unroll
    for (int k = 0; k < 4; k++) {
        int idx = tid + k * 256;
        int c   = idx >> 5;
        int tl  = (idx & 31) * 4;
        size_t off = ((size_t)(b * Cc + c)) * Tt + tBase + tl;
        float4 a  = *(const float4*)(g_sA + off);
        float4 bq = *(const float4*)(g_sB + off);
        float v0 = a.x + bq.x, v1 = a.y + bq.y, v2 = a.z + bq.z, v3 = a.w + bq.w;
        float4* d = (float4*)&dssm[c][tl];
        d[0] = make_float4(v0, v0, v1, v1);
        d[1] = make_float4(v2, v2, v3, v3);
    }
    #pragma unroll
    for (int k = 0; k < 4; k++) {
        int idx = tid + k * 256;
        int c   = idx >> 5;
        int e4  = (idx & 31) * 4;
        *(float4*)&wsm[c][e4] = *(const float4*)(g_wc + (size_t)c * Dd + eBase + e4);
    }
    __syncthreads();

    unsigned long long acc[8][4];
    #pragma unroll
    for (int i = 0; i < 8; i++)
        #pragma unroll
        for (int p = 0; p < 4; p++) acc[i][p] = 0ull;

    #pragma unroll
    for (int c = 0; c < Cc; c++) {
        const ulonglong2* sp = (const ulonglong2*)&dssm[c][ty * 8];
        ulonglong2 s01 = sp[0];
        ulonglong2 s23 = sp[1];
        ulonglong2 s45 = sp[2];
        ulonglong2 s67 = sp[3];
        unsigned long long sv[8] = {s01.x, s01.y, s23.x, s23.y,
                                    s45.x, s45.y, s67.x, s67.y};
        ulonglong2 w0 = *(const ulonglong2*)&wsm[c][4 * tx];
        ulonglong2 w1 = *(const ulonglong2*)&wsm[c][4 * tx + 64];
        #pragma unroll
        for (int i = 0; i < 8; i++) {
            FMA_F32X2(acc[i][0], sv[i], w0.x, acc[i][0]);
            FMA_F32X2(acc[i][1], sv[i], w0.y, acc[i][1]);
            FMA_F32X2(acc[i][2], sv[i], w1.x, acc[i][2]);
            FMA_F32X2(acc[i][3], sv[i], w1.y, acc[i][3]);
        }
    }

    float4 bias0 = *(const float4*)(g_bcomb + eBase + 4 * tx);
    float4 bias1 = *(const float4*)(g_bcomb + eBase + 4 * tx + 64);

    #pragma unroll
    for (int i = 0; i < 8; i++) {
        int t = tBase + ty * 8 + i;
        float* base = out + ((size_t)(b * Tt + t)) * Dd + eBase;
        float2 r0 = unpack_f32x2(acc[i][0]);
        float2 r1 = unpack_f32x2(acc[i][1]);
        float2 r2 = unpack_f32x2(acc[i][2]);
        float2 r3 = unpack_f32x2(acc[i][3]);
        float4 o0 = make_float4(r0.x + bias0.x, r0.y + bias0.y,
                                r1.x + bias0.z, r1.y + bias0.w);
        float4 o1 = make_float4(r2.x + bias1.x, r2.y + bias1.y,
                                r3.x + bias1.z, r3.y + bias1.w);
        *(float4*)(base + 4 * tx)      = o0;
        *(float4*)(base + 4 * tx + 64) = o1;
    }
}

// ---------------------------------------------------------------------------
extern "C" void kernel_launch(void* const* d_in, const int* in_sizes, int n_in,
                              void* d_out, int out_size)
{
    const float* x     = (const float*)d_in[0];   // [B, C, T]
    const float* W_ve  = (const float*)d_in[1];   // [D, C]
    const float* b_ve  = (const float*)d_in[2];   // [D]
    const float* W_lin = (const float*)d_in[3];   // [D, D]
    const float* b_lin = (const float*)d_in[4];   // [D]
    float* out = (float*)d_out;                   // [B, T, D]

    scan_kernel<<<NSCAN_BLK, 256>>>(x);
    prep_kernel<<<Dd / PE, 256>>>(W_ve, b_ve, W_lin, b_lin);

    dim3 grid(Tt / 128, Dd / 128, Bb);
    gemm_kernel<<<grid, 256>>>(out);
}

// round 10
// speedup vs baseline: 1.7393x; 1.1904x over previous
#include <cuda_runtime.h>
#include <cstdint>

#define Bb 32
#define Cc 32
#define Tt 2048
#define Dd 512
#define ALPHA 0.1f
#define BETA  0.9f

#define SEG   256
#define NSEG  (Tt / SEG)          // 8

// Scratch (no cudaMalloc allowed)
__device__ float g_sA[Bb*Cc*Tt];      // 0.5 * forward EWMA of diff   [b][c][t]
__device__ float g_sB[Bb*Cc*Tt];      // 0.5 * backward EWMA of diff  [b][c][t]
__device__ float g_wc[Cc*Dd];         // Wcomb c-major: g_wc[c*Dd + e]
__device__ float g_bcomb[Dd];         // W_lin @ b_ve + b_lin

#define FMA_F32X2(d, a, b, c) \
    asm("fma.rn.f32x2 %0, %1, %2, %3;" : "=l"(d) : "l"(a), "l"(b), "l"(c))
#define PACK_DUP(d, f) \
    asm("mov.b64 %0, {%1, %1};" : "=l"(d) : "f"(f))

static __device__ __forceinline__ float2 unpack_f32x2(unsigned long long v) {
    float2 r;
    asm("mov.b64 {%0, %1}, %2;" : "=f"(r.x), "=f"(r.y) : "l"(v));
    return r;
}

// ---------------------------------------------------------------------------
// P: smem-tiled mini-GEMM for Wcomb = W_lin @ W_ve (c-major out) + bias.
// (R9 version, measured ~4us.)
// ---------------------------------------------------------------------------
#define PE 16
__global__ void __launch_bounds__(256) prep_kernel(
    const float* __restrict__ W_ve, const float* __restrict__ b_ve,
    const float* __restrict__ W_lin, const float* __restrict__ b_lin)
{
    __shared__ float wlin_sm[128 * 17];
    __shared__ float wve_sm[128 * 36];

    int tid = threadIdx.x;
    int e0 = blockIdx.x * PE;
    int tx = tid & 15;
    int ty = tid >> 4;

    float2 acc = make_float2(0.f, 0.f);

    for (int ch = 0; ch < 4; ch++) {
        int dBase = ch * 128;
        __syncthreads();

        #pragma unroll
        for (int k = 0; k < 2; k++) {
            int idx = tid + k * 256;
            int e   = idx >> 5;
            int d4  = (idx & 31) * 4;
            float4 w = *(const float4*)(W_lin + (size_t)(e0 + e) * Dd + dBase + d4);
            wlin_sm[(d4 + 0) * 17 + e] = w.x;
            wlin_sm[(d4 + 1) * 17 + e] = w.y;
            wlin_sm[(d4 + 2) * 17 + e] = w.z;
            wlin_sm[(d4 + 3) * 17 + e] = w.w;
        }
        #pragma unroll
        for (int k = 0; k < 4; k++) {
            int idx = tid + k * 256;
            int d   = idx >> 3;
            int c4  = (idx & 7) * 4;
            float4 v = *(const float4*)(W_ve + (size_t)(dBase + d) * Cc + c4);
            *(float4*)&wve_sm[d * 36 + c4] = v;
        }
        __syncthreads();

        #pragma unroll 8
        for (int dl = 0; dl < 128; dl++) {
            float  wl  = wlin_sm[dl * 17 + ty];
            float2 wv2 = *(const float2*)&wve_sm[dl * 36 + tx * 2];
            acc.x = fmaf(wl, wv2.x, acc.x);
            acc.y = fmaf(wl, wv2.y, acc.y);
        }
    }

    int e = e0 + ty;
    g_wc[(2 * tx)     * Dd + e] = acc.x;
    g_wc[(2 * tx + 1) * Dd + e] = acc.y;

    const unsigned FULL = 0xffffffffu;
    int wid  = tid >> 5;
    int lane = tid & 31;
    #pragma unroll
    for (int r = 0; r < 2; r++) {
        int eb = e0 + 2 * wid + r;
        float a = 0.f;
        #pragma unroll
        for (int i = 0; i < 16; i++) {
            int d = lane + 32 * i;
            a = fmaf(W_lin[(size_t)eb * Dd + d], b_ve[d], a);
        }
        a += __shfl_down_sync(FULL, a, 16);
        a += __shfl_down_sync(FULL, a, 8);
        a += __shfl_down_sync(FULL, a, 4);
        a += __shfl_down_sync(FULL, a, 2);
        a += __shfl_down_sync(FULL, a, 1);
        if (lane == 0) g_bcomb[eb] = a + b_lin[eb];
    }
}

// ---------------------------------------------------------------------------
// S: bidirectional EWMA of first-difference (R3 version: SEG=256, E=8,
// measured 9.5us).
// ---------------------------------------------------------------------------
__global__ void __launch_bounds__(256) scan_kernel(const float* __restrict__ x)
{
    const unsigned FULL = 0xffffffffu;
    int g    = blockIdx.x * 8 + (threadIdx.x >> 5);
    int lane = threadIdx.x & 31;
    int bc   = g >> 4;           // row (b*Cc + c)
    int rem  = g & 15;
    int seg  = rem >> 1;
    int dir  = rem & 1;

    const float* row = x + (size_t)bc * Tt;
    int lo = seg * SEG;
    int hi = lo + SEG;

    const float q   = 0.43046721f;              // 0.9^8
    const float q2  = q * q;
    const float q4  = q2 * q2;
    const float q8  = q4 * q4;
    const float q16 = q8 * q8;
    float blE;
    {
        float p = 1.f, base = q;
        int n = lane;
        while (n) { if (n & 1) p *= base; base *= base; n >>= 1; }
        blE = p;
    }
    const float B256 = 1.9e-12f;

    if (dir == 0) {
        float* srow = g_sA + (size_t)bc * Tt;
        int t0 = (seg == 0) ? lo : (lo - SEG);
        float warpCarry = 0.f;
        for (; t0 < hi; t0 += SEG) {
            int tb = t0 + lane * 8;
            float4 a  = *(const float4*)(row + tb);
            float4 bq = *(const float4*)(row + tb + 4);
            float e[8] = {a.x, a.y, a.z, a.w, bq.x, bq.y, bq.z, bq.w};
            float prev = __shfl_up_sync(FULL, bq.w, 1);
            if (lane == 0) prev = (tb > 0) ? row[tb - 1] : 0.f;

            float L[8];
            L[0] = (tb == 0) ? 0.f : ALPHA * (e[0] - prev);
            #pragma unroll
            for (int j = 1; j < 8; j++)
                L[j] = fmaf(BETA, L[j - 1], ALPHA * (e[j] - e[j - 1]));

            float v = L[7], vo;
            vo = __shfl_up_sync(FULL, v, 1);  if (lane >= 1)  v = fmaf(q,   vo, v);
            vo = __shfl_up_sync(FULL, v, 2);  if (lane >= 2)  v = fmaf(q2,  vo, v);
            vo = __shfl_up_sync(FULL, v, 4);  if (lane >= 4)  v = fmaf(q4,  vo, v);
            vo = __shfl_up_sync(FULL, v, 8);  if (lane >= 8)  v = fmaf(q8,  vo, v);
            vo = __shfl_up_sync(FULL, v, 16); if (lane >= 16) v = fmaf(q16, vo, v);
            float vprev = __shfl_up_sync(FULL, v, 1);
            if (lane == 0) vprev = 0.f;
            float C = fmaf(blE, warpCarry, vprev);

            float F[8];
            float coef = BETA;
            #pragma unroll
            for (int j = 0; j < 8; j++) { F[j] = fmaf(coef, C, L[j]); coef *= BETA; }
            float v31 = __shfl_sync(FULL, v, 31);
            warpCarry = fmaf(B256, warpCarry, v31);

            if (t0 >= lo) {
                *(float4*)(srow + tb)     = make_float4(0.5f*F[0], 0.5f*F[1], 0.5f*F[2], 0.5f*F[3]);
                *(float4*)(srow + tb + 4) = make_float4(0.5f*F[4], 0.5f*F[5], 0.5f*F[6], 0.5f*F[7]);
            }
        }
    } else {
        float* srow = g_sB + (size_t)bc * Tt;
        bool last = (hi == Tt);
        int tt = last ? (Tt - 1) : (hi + SEG - 1);
        float warpCarry = last ? (row[Tt - 1] - row[Tt - 2]) : 0.f;
        for (; tt >= lo; tt -= SEG) {
            int tb = tt - lane * 8;
            float4 a  = *(const float4*)(row + tb - 7);
            float4 bq = *(const float4*)(row + tb - 3);
            float e[8] = {bq.w, bq.z, bq.y, bq.x, a.w, a.z, a.y, a.x};
            float prev = __shfl_down_sync(FULL, bq.w, 1);
            if (lane == 31) prev = (tb - 8 >= 0) ? row[tb - 8] : 0.f;

            float L[8];
            L[0] = ALPHA * (e[0] - e[1]);
            #pragma unroll
            for (int j = 1; j < 7; j++)
                L[j] = fmaf(BETA, L[j - 1], ALPHA * (e[j] - e[j + 1]));
            {
                float d7 = (tb - 7 == 0) ? 0.f : (e[7] - prev);
                L[7] = fmaf(BETA, L[6], ALPHA * d7);
            }

            float v = L[7], vo;
            vo = __shfl_up_sync(FULL, v, 1);  if (lane >= 1)  v = fmaf(q,   vo, v);
            vo = __shfl_up_sync(FULL, v, 2);  if (lane >= 2)  v = fmaf(q2,  vo, v);
            vo = __shfl_up_sync(FULL, v, 4);  if (lane >= 4)  v = fmaf(q4,  vo, v);
            vo = __shfl_up_sync(FULL, v, 8);  if (lane >= 8)  v = fmaf(q8,  vo, v);
            vo = __shfl_up_sync(FULL, v, 16); if (lane >= 16) v = fmaf(q16, vo, v);
            float vprev = __shfl_up_sync(FULL, v, 1);
            if (lane == 0) vprev = 0.f;
            float C = fmaf(blE, warpCarry, vprev);

            float F[8];
            float coef = BETA;
            #pragma unroll
            for (int j = 0; j < 8; j++) { F[j] = fmaf(coef, C, L[j]); coef *= BETA; }
            float v31 = __shfl_sync(FULL, v, 31);
            warpCarry = fmaf(B256, warpCarry, v31);

            if (tt < hi) {
                *(float4*)(srow + tb - 7) = make_float4(0.5f*F[7], 0.5f*F[6], 0.5f*F[5], 0.5f*F[4]);
                *(float4*)(srow + tb - 3) = make_float4(0.5f*F[3], 0.5f*F[2], 0.5f*F[1], 0.5f*F[0]);
            }
        }
    }
}

// ---------------------------------------------------------------------------
// G: register-blocked FFMA2 GEMM, s tile stored NATURAL (no duplication).
// Per c per thread: 2 LDS.128 (s, 8 floats) + 2 LDS.128 (w pairs)
// + 8 reg dup-packs (alu) + 32 FFMA2. smem traffic -33% vs R8.
// Block tile 128t x 128e, thread tile 8t x 8e (e = 4*tx + 64*p + j).
// ---------------------------------------------------------------------------
__global__ void __launch_bounds__(256, 2) gemm_kernel(float* __restrict__ out)
{
    __shared__ float ssm[Cc][128];     // [c][t_local] natural, 16 KB
    __shared__ float wsm[Cc][128];     // [c][e_local] natural, 16 KB

    int tid = threadIdx.x;
    int tx = tid & 15;
    int ty = tid >> 4;
    int b = blockIdx.z;
    int eBase = blockIdx.y * 128;
    int tBase = blockIdx.x * 128;

    // Stage s: 32c x 128t, coalesced float4 over t.
    #pragma unroll
    for (int k = 0; k < 4; k++) {
        int idx = tid + k * 256;          // 0..1023
        int c   = idx >> 5;               // 0..31
        int tl  = (idx & 31) * 4;         // 0..124
        size_t off = ((size_t)(b * Cc + c)) * Tt + tBase + tl;
        float4 a  = *(const float4*)(g_sA + off);
        float4 bq = *(const float4*)(g_sB + off);
        *(float4*)&ssm[c][tl] = make_float4(a.x + bq.x, a.y + bq.y,
                                            a.z + bq.z, a.w + bq.w);
    }
    // Stage w: 32c x 128e.
    #pragma unroll
    for (int k = 0; k < 4; k++) {
        int idx = tid + k * 256;
        int c   = idx >> 5;
        int e4  = (idx & 31) * 4;
        *(float4*)&wsm[c][e4] = *(const float4*)(g_wc + (size_t)c * Dd + eBase + e4);
    }
    __syncthreads();

    unsigned long long acc[8][4];
    #pragma unroll
    for (int i = 0; i < 8; i++)
        #pragma unroll
        for (int p = 0; p < 4; p++) acc[i][p] = 0ull;

    #pragma unroll
    for (int c = 0; c < Cc; c++) {
        float4 s0 = *(const float4*)&ssm[c][ty * 8];
        float4 s1 = *(const float4*)&ssm[c][ty * 8 + 4];
        float sf[8] = {s0.x, s0.y, s0.z, s0.w, s1.x, s1.y, s1.z, s1.w};
        unsigned long long sv[8];
        #pragma unroll
        for (int i = 0; i < 8; i++) PACK_DUP(sv[i], sf[i]);

        ulonglong2 w0 = *(const ulonglong2*)&wsm[c][4 * tx];        // e (0,1),(2,3)
        ulonglong2 w1 = *(const ulonglong2*)&wsm[c][4 * tx + 64];
        #pragma unroll
        for (int i = 0; i < 8; i++) {
            FMA_F32X2(acc[i][0], sv[i], w0.x, acc[i][0]);
            FMA_F32X2(acc[i][1], sv[i], w0.y, acc[i][1]);
            FMA_F32X2(acc[i][2], sv[i], w1.x, acc[i][2]);
            FMA_F32X2(acc[i][3], sv[i], w1.y, acc[i][3]);
        }
    }

    float4 bias0 = *(const float4*)(g_bcomb + eBase + 4 * tx);
    float4 bias1 = *(const float4*)(g_bcomb + eBase + 4 * tx + 64);

    #pragma unroll
    for (int i = 0; i < 8; i++) {
        int t = tBase + ty * 8 + i;
        float* base = out + ((size_t)(b * Tt + t)) * Dd + eBase;
        float2 r0 = unpack_f32x2(acc[i][0]);
        float2 r1 = unpack_f32x2(acc[i][1]);
        float2 r2 = unpack_f32x2(acc[i][2]);
        float2 r3 = unpack_f32x2(acc[i][3]);
        float4 o0 = make_float4(r0.x + bias0.x, r0.y + bias0.y,
                                r1.x + bias0.z, r1.y + bias0.w);
        float4 o1 = make_float4(r2.x + bias1.x, r2.y + bias1.y,
                                r3.x + bias1.z, r3.y + bias1.w);
        *(float4*)(base + 4 * tx)      = o0;
        *(float4*)(base + 4 * tx + 64) = o1;
    }
}

// ---------------------------------------------------------------------------
extern "C" void kernel_launch(void* const* d_in, const int* in_sizes, int n_in,
                              void* d_out, int out_size)
{
    const float* x     = (const float*)d_in[0];   // [B, C, T]
    const float* W_ve  = (const float*)d_in[1];   // [D, C]
    const float* b_ve  = (const float*)d_in[2];   // [D]
    const float* W_lin = (const float*)d_in[3];   // [D, D]
    const float* b_lin = (const float*)d_in[4];   // [D]
    float* out = (float*)d_out;                   // [B, T, D]

    scan_kernel<<<(Bb * Cc * NSEG * 2) / 8, 256>>>(x);
    prep_kernel<<<Dd / PE, 256>>>(W_ve, b_ve, W_lin, b_lin);

    dim3 grid(Tt / 128, Dd / 128, Bb);
    gemm_kernel<<<grid, 256>>>(out);
}